// round 14
// baseline (speedup 1.0000x reference)
#include <cuda_runtime.h>

#define Nn 10000
#define Ee 320000
#define EA (Ee + Nn)
#define HID 256

// ---------------- scratch (static device globals; no allocations) ----------
__device__ __align__(16) float g_xl[Nn * HID];
__device__ __align__(16) float g_xr[Nn * HID];
__device__ __align__(16) float g_h [Nn * HID];
__device__ __align__(16) float g_h2[Nn * HID];
__device__ int          g_cnt[Nn];
__device__ int          g_cur[Nn];
__device__ int          g_rowptr[Nn + 1];
__device__ int          g_csrc[EA];
__device__ float        g_cea[EA];
__device__ float        g_loop[Nn];
__device__ float        g_plog[Nn * 4];
__device__ unsigned int g_gmax;
__device__ float        g_gsum;

// ---------------- helpers ---------------------------------------------------
__device__ __forceinline__ unsigned int fenc(float x) {
    unsigned int u = __float_as_uint(x);
    return (u & 0x80000000u) ? ~u : (u | 0x80000000u);
}
__device__ __forceinline__ float fdec(unsigned int e) {
    return __uint_as_float((e & 0x80000000u) ? (e & 0x7FFFFFFFu) : ~e);
}
__device__ __forceinline__ float lrelu(float x) { return x > 0.f ? x : 0.2f * x; }

__device__ __forceinline__ float logit8(float4 a0, float4 a1, float4 b0, float4 b1,
                                        float ea, float4 w0, float4 w1,
                                        float4 t0, float4 t1) {
    float p;
    p  = lrelu(a0.x + b0.x + ea * w0.x) * t0.x;
    p += lrelu(a0.y + b0.y + ea * w0.y) * t0.y;
    p += lrelu(a0.z + b0.z + ea * w0.z) * t0.z;
    p += lrelu(a0.w + b0.w + ea * w0.w) * t0.w;
    p += lrelu(a1.x + b1.x + ea * w1.x) * t1.x;
    p += lrelu(a1.y + b1.y + ea * w1.y) * t1.y;
    p += lrelu(a1.z + b1.z + ea * w1.z) * t1.z;
    p += lrelu(a1.w + b1.w + ea * w1.w) * t1.w;
    return p;
}

// ---------------- init -------------------------------------------------------
__global__ void k_init() {
    int i = blockIdx.x * blockDim.x + threadIdx.x;
    if (i < Nn) { g_cnt[i] = 0; g_cur[i] = 0; g_loop[i] = 0.f; }
    if (i == 0) { g_gmax = 0u; g_gsum = 0.f; }
}

// ---------------- conv1 linear: x [N,4] @ W [4,256] + b ---------------------
__global__ void k_lin1(const float* __restrict__ x,
                       const float* __restrict__ Wl, const float* __restrict__ bl,
                       const float* __restrict__ Wr, const float* __restrict__ br) {
    int idx = blockIdx.x * blockDim.x + threadIdx.x;
    if (idx >= Nn * HID) return;
    int i = idx >> 8, j = idx & 255;
    float x0 = x[i * 4], x1 = x[i * 4 + 1], x2 = x[i * 4 + 2], x3 = x[i * 4 + 3];
    g_xl[idx] = x0 * Wl[j] + x1 * Wl[256 + j] + x2 * Wl[512 + j] + x3 * Wl[768 + j] + bl[j];
    g_xr[idx] = x0 * Wr[j] + x1 * Wr[256 + j] + x2 * Wr[512 + j] + x3 * Wr[768 + j] + br[j];
}

// ---------------- CSR build --------------------------------------------------
__global__ void k_deg(const int* __restrict__ ei, const float* __restrict__ eat) {
    int e = blockIdx.x * blockDim.x + threadIdx.x;
    if (e >= Ee) return;
    int d = ei[Ee + e];
    atomicAdd(&g_cnt[d], 1);
    atomicAdd(&g_loop[d], eat[e]);
}

// exclusive scan of (cnt[i]+1) -> rowptr via warp shuffles; finish loop mean.
__global__ void k_scan() {
    __shared__ int wsum[32];
    int t = threadIdx.x;
    int lane = t & 31, wid = t >> 5;
    int base = t * 10;
    int local[10];
    int s = 0;
    #pragma unroll
    for (int k = 0; k < 10; k++) {
        int idx = base + k;
        int v = 0;
        if (idx < Nn) {
            v = g_cnt[idx] + 1;
            g_loop[idx] /= fmaxf((float)(v - 1), 1.0f);
        }
        local[k] = s;
        s += v;
    }
    // warp-inclusive scan of per-thread totals
    int inc = s;
    #pragma unroll
    for (int off = 1; off < 32; off <<= 1) {
        int u = __shfl_up_sync(0xffffffffu, inc, off);
        if (lane >= off) inc += u;
    }
    if (lane == 31) wsum[wid] = inc;
    __syncthreads();
    if (wid == 0) {
        int w = wsum[lane];
        #pragma unroll
        for (int off = 1; off < 32; off <<= 1) {
            int u = __shfl_up_sync(0xffffffffu, w, off);
            if (lane >= off) w += u;
        }
        wsum[lane] = w;
    }
    __syncthreads();
    int offset = inc - s + (wid ? wsum[wid - 1] : 0);
    #pragma unroll
    for (int k = 0; k < 10; k++) {
        int idx = base + k;
        if (idx < Nn) g_rowptr[idx] = offset + local[k];
    }
    if (t == 1023) g_rowptr[Nn] = wsum[31];
}

// scatter edges + self-loops in one launch
__global__ void k_scatter(const int* __restrict__ ei, const float* __restrict__ eat) {
    int e = blockIdx.x * blockDim.x + threadIdx.x;
    if (e < Ee) {
        int d = ei[Ee + e];
        int pos = g_rowptr[d] + atomicAdd(&g_cur[d], 1);
        g_csrc[pos] = ei[e];
        g_cea[pos]  = eat[e];
    } else if (e < EA) {
        int i = e - Ee;
        int pos = g_rowptr[i + 1] - 1;
        g_csrc[pos] = i;
        g_cea[pos]  = g_loop[i];
    }
}

// ---------------- fused convs: dual-state online softmax (unchanged R9 win) --
__global__ __launch_bounds__(128) void k_conv1(const float* __restrict__ We,
                                               const float* __restrict__ att) {
    int node = (blockIdx.x * blockDim.x + threadIdx.x) >> 5;
    if (node >= Nn) return;
    int lane = threadIdx.x & 31;
    int c0 = lane * 8;
    float4 b0 = *(const float4*)&g_xr[node * HID + c0];
    float4 b1 = *(const float4*)&g_xr[node * HID + c0 + 4];
    float4 w0 = *(const float4*)&We[c0];
    float4 w1 = *(const float4*)&We[c0 + 4];
    float4 t0 = *(const float4*)&att[c0];
    float4 t1 = *(const float4*)&att[c0 + 4];
    float mxA = -3.4e38f, denA = 0.f;
    float mxB = -3.4e38f, denB = 0.f;
    float4 aA0 = {0,0,0,0}, aA1 = {0,0,0,0};
    float4 aB0 = {0,0,0,0}, aB1 = {0,0,0,0};
    int j0 = g_rowptr[node], j1 = g_rowptr[node + 1];
    int n = j1 - j0;
    int j = j0;
    for (int it = 0; it < (n >> 1); it++, j += 2) {
        int sA = g_csrc[j], sB = g_csrc[j + 1];
        float eaA = g_cea[j], eaB = g_cea[j + 1];
        float4 fA0 = *(const float4*)&g_xl[sA * HID + c0];
        float4 fA1 = *(const float4*)&g_xl[sA * HID + c0 + 4];
        float4 fB0 = *(const float4*)&g_xl[sB * HID + c0];
        float4 fB1 = *(const float4*)&g_xl[sB * HID + c0 + 4];
        float pA = logit8(fA0, fA1, b0, b1, eaA, w0, w1, t0, t1);
        float pB = logit8(fB0, fB1, b0, b1, eaB, w0, w1, t0, t1);
        pA += __shfl_xor_sync(0xffffffffu, pA, 1);
        pB += __shfl_xor_sync(0xffffffffu, pB, 1);
        pA += __shfl_xor_sync(0xffffffffu, pA, 2);
        pB += __shfl_xor_sync(0xffffffffu, pB, 2);
        pA += __shfl_xor_sync(0xffffffffu, pA, 4);
        pB += __shfl_xor_sync(0xffffffffu, pB, 4);
        float nmA = fmaxf(mxA, pA), nmB = fmaxf(mxB, pB);
        float scA = __expf(mxA - nmA), scB = __expf(mxB - nmB);
        float peA = __expf(pA - nmA), peB = __expf(pB - nmB);
        denA = denA * scA + peA;           denB = denB * scB + peB;
        aA0.x = aA0.x * scA + peA * fA0.x; aB0.x = aB0.x * scB + peB * fB0.x;
        aA0.y = aA0.y * scA + peA * fA0.y; aB0.y = aB0.y * scB + peB * fB0.y;
        aA0.z = aA0.z * scA + peA * fA0.z; aB0.z = aB0.z * scB + peB * fB0.z;
        aA0.w = aA0.w * scA + peA * fA0.w; aB0.w = aB0.w * scB + peB * fB0.w;
        aA1.x = aA1.x * scA + peA * fA1.x; aB1.x = aB1.x * scB + peB * fB1.x;
        aA1.y = aA1.y * scA + peA * fA1.y; aB1.y = aB1.y * scB + peB * fB1.y;
        aA1.z = aA1.z * scA + peA * fA1.z; aB1.z = aB1.z * scB + peB * fB1.z;
        aA1.w = aA1.w * scA + peA * fA1.w; aB1.w = aB1.w * scB + peB * fB1.w;
        mxA = nmA; mxB = nmB;
    }
    if (n & 1) {
        int sA = g_csrc[j];
        float eaA = g_cea[j];
        float4 fA0 = *(const float4*)&g_xl[sA * HID + c0];
        float4 fA1 = *(const float4*)&g_xl[sA * HID + c0 + 4];
        float pA = logit8(fA0, fA1, b0, b1, eaA, w0, w1, t0, t1);
        pA += __shfl_xor_sync(0xffffffffu, pA, 1);
        pA += __shfl_xor_sync(0xffffffffu, pA, 2);
        pA += __shfl_xor_sync(0xffffffffu, pA, 4);
        float nmA = fmaxf(mxA, pA);
        float scA = __expf(mxA - nmA);
        float peA = __expf(pA - nmA);
        denA = denA * scA + peA;
        aA0.x = aA0.x * scA + peA * fA0.x;
        aA0.y = aA0.y * scA + peA * fA0.y;
        aA0.z = aA0.z * scA + peA * fA0.z;
        aA0.w = aA0.w * scA + peA * fA0.w;
        aA1.x = aA1.x * scA + peA * fA1.x;
        aA1.y = aA1.y * scA + peA * fA1.y;
        aA1.z = aA1.z * scA + peA * fA1.z;
        aA1.w = aA1.w * scA + peA * fA1.w;
        mxA = nmA;
    }
    float nm = fmaxf(mxA, mxB);
    float sA = __expf(mxA - nm), sB = __expf(mxB - nm);
    float inv = 1.0f / (denA * sA + denB * sB);
    float4 o0, o1;
    o0.x = (aA0.x * sA + aB0.x * sB) * inv;
    o0.y = (aA0.y * sA + aB0.y * sB) * inv;
    o0.z = (aA0.z * sA + aB0.z * sB) * inv;
    o0.w = (aA0.w * sA + aB0.w * sB) * inv;
    o1.x = (aA1.x * sA + aB1.x * sB) * inv;
    o1.y = (aA1.y * sA + aB1.y * sB) * inv;
    o1.z = (aA1.z * sA + aB1.z * sB) * inv;
    o1.w = (aA1.w * sA + aB1.w * sB) * inv;
    *(float4*)&g_h[node * HID + c0]     = o0;
    *(float4*)&g_h[node * HID + c0 + 4] = o1;
}

__global__ __launch_bounds__(128) void k_conv2(const float* __restrict__ We,
                                               const float* __restrict__ att) {
    int node = (blockIdx.x * blockDim.x + threadIdx.x) >> 5;
    if (node >= Nn) return;
    int lane = threadIdx.x & 31;
    int c0 = lane * 8;
    float4 b0 = *(const float4*)&g_xr[node * HID + c0];
    float4 b1 = *(const float4*)&g_xr[node * HID + c0 + 4];
    float4 w0 = *(const float4*)&We[c0];
    float4 w1 = *(const float4*)&We[c0 + 4];
    float4 t0 = *(const float4*)&att[c0];
    float4 t1 = *(const float4*)&att[c0 + 4];
    float mxA = -3.4e38f, denA = 0.f;
    float mxB = -3.4e38f, denB = 0.f;
    float4 aA0 = {0,0,0,0}, aA1 = {0,0,0,0};
    float4 aB0 = {0,0,0,0}, aB1 = {0,0,0,0};
    int j0 = g_rowptr[node], j1 = g_rowptr[node + 1];
    int n = j1 - j0;
    int j = j0;
    for (int it = 0; it < (n >> 1); it++, j += 2) {
        int sA = g_csrc[j], sB = g_csrc[j + 1];
        float eaA = g_cea[j], eaB = g_cea[j + 1];
        float4 fA0 = *(const float4*)&g_xl[sA * HID + c0];
        float4 fA1 = *(const float4*)&g_xl[sA * HID + c0 + 4];
        float4 fB0 = *(const float4*)&g_xl[sB * HID + c0];
        float4 fB1 = *(const float4*)&g_xl[sB * HID + c0 + 4];
        float pA = logit8(fA0, fA1, b0, b1, eaA, w0, w1, t0, t1);
        float pB = logit8(fB0, fB1, b0, b1, eaB, w0, w1, t0, t1);
        #pragma unroll
        for (int off = 16; off; off >>= 1) {
            pA += __shfl_xor_sync(0xffffffffu, pA, off);
            pB += __shfl_xor_sync(0xffffffffu, pB, off);
        }
        float nmA = fmaxf(mxA, pA), nmB = fmaxf(mxB, pB);
        float scA = __expf(mxA - nmA), scB = __expf(mxB - nmB);
        float peA = __expf(pA - nmA), peB = __expf(pB - nmB);
        denA = denA * scA + peA;           denB = denB * scB + peB;
        aA0.x = aA0.x * scA + peA * fA0.x; aB0.x = aB0.x * scB + peB * fB0.x;
        aA0.y = aA0.y * scA + peA * fA0.y; aB0.y = aB0.y * scB + peB * fB0.y;
        aA0.z = aA0.z * scA + peA * fA0.z; aB0.z = aB0.z * scB + peB * fB0.z;
        aA0.w = aA0.w * scA + peA * fA0.w; aB0.w = aB0.w * scB + peB * fB0.w;
        aA1.x = aA1.x * scA + peA * fA1.x; aB1.x = aB1.x * scB + peB * fB1.x;
        aA1.y = aA1.y * scA + peA * fA1.y; aB1.y = aB1.y * scB + peB * fB1.y;
        aA1.z = aA1.z * scA + peA * fA1.z; aB1.z = aB1.z * scB + peB * fB1.z;
        aA1.w = aA1.w * scA + peA * fA1.w; aB1.w = aB1.w * scB + peB * fB1.w;
        mxA = nmA; mxB = nmB;
    }
    if (n & 1) {
        int sA = g_csrc[j];
        float eaA = g_cea[j];
        float4 fA0 = *(const float4*)&g_xl[sA * HID + c0];
        float4 fA1 = *(const float4*)&g_xl[sA * HID + c0 + 4];
        float pA = logit8(fA0, fA1, b0, b1, eaA, w0, w1, t0, t1);
        #pragma unroll
        for (int off = 16; off; off >>= 1) pA += __shfl_xor_sync(0xffffffffu, pA, off);
        float nmA = fmaxf(mxA, pA);
        float scA = __expf(mxA - nmA);
        float peA = __expf(pA - nmA);
        denA = denA * scA + peA;
        aA0.x = aA0.x * scA + peA * fA0.x;
        aA0.y = aA0.y * scA + peA * fA0.y;
        aA0.z = aA0.z * scA + peA * fA0.z;
        aA0.w = aA0.w * scA + peA * fA0.w;
        aA1.x = aA1.x * scA + peA * fA1.x;
        aA1.y = aA1.y * scA + peA * fA1.y;
        aA1.z = aA1.z * scA + peA * fA1.z;
        aA1.w = aA1.w * scA + peA * fA1.w;
        mxA = nmA;
    }
    float nm = fmaxf(mxA, mxB);
    float sA = __expf(mxA - nm), sB = __expf(mxB - nm);
    float inv = 1.0f / (denA * sA + denB * sB);
    float4 o0, o1;
    o0.x = (aA0.x * sA + aB0.x * sB) * inv;
    o0.y = (aA0.y * sA + aB0.y * sB) * inv;
    o0.z = (aA0.z * sA + aB0.z * sB) * inv;
    o0.w = (aA0.w * sA + aB0.w * sB) * inv;
    o1.x = (aA1.x * sA + aB1.x * sB) * inv;
    o1.y = (aA1.y * sA + aB1.y * sB) * inv;
    o1.z = (aA1.z * sA + aB1.z * sB) * inv;
    o1.w = (aA1.w * sA + aB1.w * sB) * inv;
    *(float4*)&g_h2[node * HID + c0]     = o0;
    *(float4*)&g_h2[node * HID + c0 + 4] = o1;
}

// layernorm(in + bias) * g + b, then relu.  One warp per node.
__global__ void k_ln_relu(const float* __restrict__ inp, float* __restrict__ outp,
                          const float* __restrict__ bias, const float* __restrict__ gam,
                          const float* __restrict__ bet) {
    int w = (blockIdx.x * blockDim.x + threadIdx.x) >> 5;
    if (w >= Nn) return;
    int lane = threadIdx.x & 31, c0 = lane * 8;
    float v[8];
    float4 p0 = *(const float4*)&inp[w * HID + c0];
    float4 p1 = *(const float4*)&inp[w * HID + c0 + 4];
    float4 q0 = *(const float4*)&bias[c0];
    float4 q1 = *(const float4*)&bias[c0 + 4];
    v[0] = p0.x + q0.x; v[1] = p0.y + q0.y; v[2] = p0.z + q0.z; v[3] = p0.w + q0.w;
    v[4] = p1.x + q1.x; v[5] = p1.y + q1.y; v[6] = p1.z + q1.z; v[7] = p1.w + q1.w;
    float s = 0.f;
    #pragma unroll
    for (int k = 0; k < 8; k++) s += v[k];
    #pragma unroll
    for (int off = 16; off; off >>= 1) s += __shfl_xor_sync(0xffffffffu, s, off);
    float mu = s * (1.0f / HID);
    float q = 0.f;
    #pragma unroll
    for (int k = 0; k < 8; k++) { float t = v[k] - mu; q += t * t; }
    #pragma unroll
    for (int off = 16; off; off >>= 1) q += __shfl_xor_sync(0xffffffffu, q, off);
    float r = rsqrtf(q * (1.0f / HID) + 1e-5f);
    float4 go0 = *(const float4*)&gam[c0];
    float4 go1 = *(const float4*)&gam[c0 + 4];
    float4 bo0 = *(const float4*)&bet[c0];
    float4 bo1 = *(const float4*)&bet[c0 + 4];
    float4 o0, o1;
    o0.x = fmaxf((v[0] - mu) * r * go0.x + bo0.x, 0.f);
    o0.y = fmaxf((v[1] - mu) * r * go0.y + bo0.y, 0.f);
    o0.z = fmaxf((v[2] - mu) * r * go0.z + bo0.z, 0.f);
    o0.w = fmaxf((v[3] - mu) * r * go0.w + bo0.w, 0.f);
    o1.x = fmaxf((v[4] - mu) * r * go1.x + bo1.x, 0.f);
    o1.y = fmaxf((v[5] - mu) * r * go1.y + bo1.y, 0.f);
    o1.z = fmaxf((v[6] - mu) * r * go1.z + bo1.z, 0.f);
    o1.w = fmaxf((v[7] - mu) * r * go1.w + bo1.w, 0.f);
    *(float4*)&outp[w * HID + c0]     = o0;
    *(float4*)&outp[w * HID + c0 + 4] = o1;
}

// ---------------- register-blocked SGEMM  C[M,N] = A[M,256] @ W[256,N] + b --
// 64x128 tile, 256 threads, 4x8 acc per thread, register prefetch.
template<int RELU>
__global__ __launch_bounds__(256) void k_sgemm(
    const float* __restrict__ A, const float* __restrict__ W,
    const float* __restrict__ bias, float* __restrict__ C, int N)
{
    __shared__ float As[8][64];
    __shared__ float Bs[8][128];
    int tid = threadIdx.x;
    int m0 = blockIdx.x * 64;
    int n0 = blockIdx.y * 128;
    int tx = tid & 15, ty = tid >> 4;
    int arow = tid >> 2, acol = (tid & 3) * 2;
    int brow = tid >> 5, bcol = (tid & 31) * 4;
    bool aval = (m0 + arow) < Nn;
    const float* Ap = A + (m0 + arow) * 256 + acol;
    const float* Wp = W + brow * N + n0 + bcol;
    float2 ra = aval ? *(const float2*)Ap : make_float2(0.f, 0.f);
    float4 rb = *(const float4*)Wp;
    float acc[4][8];
    #pragma unroll
    for (int i = 0; i < 4; i++)
        #pragma unroll
        for (int j = 0; j < 8; j++) acc[i][j] = 0.f;
    #pragma unroll 1
    for (int t = 0; t < 32; t++) {
        As[acol][arow]     = ra.x;
        As[acol + 1][arow] = ra.y;
        *(float4*)&Bs[brow][bcol] = rb;
        __syncthreads();
        if (t < 31) {
            ra = aval ? *(const float2*)(Ap + (t + 1) * 8) : make_float2(0.f, 0.f);
            rb = *(const float4*)(Wp + (t + 1) * 8 * N);
        }
        #pragma unroll
        for (int k = 0; k < 8; k++) {
            float a[4], b[8];
            *(float4*)a       = *(const float4*)&As[k][ty * 4];
            *(float4*)b       = *(const float4*)&Bs[k][tx * 8];
            *(float4*)(b + 4) = *(const float4*)&Bs[k][tx * 8 + 4];
            #pragma unroll
            for (int i = 0; i < 4; i++)
                #pragma unroll
                for (int j = 0; j < 8; j++) acc[i][j] += a[i] * b[j];
        }
        __syncthreads();
    }
    float bb[8];
    *(float4*)bb       = *(const float4*)&bias[n0 + tx * 8];
    *(float4*)(bb + 4) = *(const float4*)&bias[n0 + tx * 8 + 4];
    #pragma unroll
    for (int i = 0; i < 4; i++) {
        int row = m0 + ty * 4 + i;
        if (row < Nn) {
            float o[8];
            #pragma unroll
            for (int j = 0; j < 8; j++) {
                o[j] = acc[i][j] + bb[j];
                if (RELU) o[j] = fmaxf(o[j], 0.f);
            }
            *(float4*)&C[row * N + n0 + tx * 8]     = *(float4*)o;
            *(float4*)&C[row * N + n0 + tx * 8 + 4] = *(float4*)(o + 4);
        }
    }
}

// conv2 linears via sgemm tiles: blockIdx.y 0-1 -> Wl2 -> g_xl, 2-3 -> Wr2 -> g_xr
__global__ __launch_bounds__(256) void k_gemm2(
    const float* __restrict__ Hin,
    const float* __restrict__ Wl, const float* __restrict__ bl,
    const float* __restrict__ Wr, const float* __restrict__ br)
{
    __shared__ float As[8][64];
    __shared__ float Bs[8][128];
    int tid = threadIdx.x;
    int m0 = blockIdx.x * 64;
    int yy = blockIdx.y;
    const float* W    = (yy < 2) ? Wl : Wr;
    const float* bias = (yy < 2) ? bl : br;
    float* C          = (yy < 2) ? g_xl : g_xr;
    int n0 = (yy & 1) * 128;
    int tx = tid & 15, ty = tid >> 4;
    int arow = tid >> 2, acol = (tid & 3) * 2;
    int brow = tid >> 5, bcol = (tid & 31) * 4;
    bool aval = (m0 + arow) < Nn;
    const float* Ap = Hin + (m0 + arow) * 256 + acol;
    const float* Wp = W + brow * 256 + n0 + bcol;
    float2 ra = aval ? *(const float2*)Ap : make_float2(0.f, 0.f);
    float4 rb = *(const float4*)Wp;
    float acc[4][8];
    #pragma unroll
    for (int i = 0; i < 4; i++)
        #pragma unroll
        for (int j = 0; j < 8; j++) acc[i][j] = 0.f;
    #pragma unroll 1
    for (int t = 0; t < 32; t++) {
        As[acol][arow]     = ra.x;
        As[acol + 1][arow] = ra.y;
        *(float4*)&Bs[brow][bcol] = rb;
        __syncthreads();
        if (t < 31) {
            ra = aval ? *(const float2*)(Ap + (t + 1) * 8) : make_float2(0.f, 0.f);
            rb = *(const float4*)(Wp + (t + 1) * 8 * 256);
        }
        #pragma unroll
        for (int k = 0; k < 8; k++) {
            float a[4], b[8];
            *(float4*)a       = *(const float4*)&As[k][ty * 4];
            *(float4*)b       = *(const float4*)&Bs[k][tx * 8];
            *(float4*)(b + 4) = *(const float4*)&Bs[k][tx * 8 + 4];
            #pragma unroll
            for (int i = 0; i < 4; i++)
                #pragma unroll
                for (int j = 0; j < 8; j++) acc[i][j] += a[i] * b[j];
        }
        __syncthreads();
    }
    float bb[8];
    *(float4*)bb       = *(const float4*)&bias[n0 + tx * 8];
    *(float4*)(bb + 4) = *(const float4*)&bias[n0 + tx * 8 + 4];
    #pragma unroll
    for (int i = 0; i < 4; i++) {
        int row = m0 + ty * 4 + i;
        if (row < Nn) {
            float o[8];
            #pragma unroll
            for (int j = 0; j < 8; j++) o[j] = acc[i][j] + bb[j];
            *(float4*)&C[row * 256 + n0 + tx * 8]     = *(float4*)o;
            *(float4*)&C[row * 256 + n0 + tx * 8 + 4] = *(float4*)(o + 4);
        }
    }
}

// policy tail: logits = p1[N,128] @ Wp2[128,4] + bp2; warp per node; global max
__global__ void k_pol2(const float* __restrict__ Wp2, const float* __restrict__ bp2) {
    int node = (blockIdx.x * blockDim.x + threadIdx.x) >> 5;
    if (node >= Nn) return;
    int lane = threadIdx.x & 31;
    float4 p = *(const float4*)&g_xl[node * 128 + lane * 4];   // p1 (stride 128)
    float4 wr0 = *(const float4*)&Wp2[(lane * 4 + 0) * 4];
    float4 wr1 = *(const float4*)&Wp2[(lane * 4 + 1) * 4];
    float4 wr2 = *(const float4*)&Wp2[(lane * 4 + 2) * 4];
    float4 wr3 = *(const float4*)&Wp2[(lane * 4 + 3) * 4];
    float s0 = p.x * wr0.x + p.y * wr1.x + p.z * wr2.x + p.w * wr3.x;
    float s1 = p.x * wr0.y + p.y * wr1.y + p.z * wr2.y + p.w * wr3.y;
    float s2 = p.x * wr0.z + p.y * wr1.z + p.z * wr2.z + p.w * wr3.z;
    float s3 = p.x * wr0.w + p.y * wr1.w + p.z * wr2.w + p.w * wr3.w;
    #pragma unroll
    for (int off = 16; off; off >>= 1) {
        s0 += __shfl_xor_sync(0xffffffffu, s0, off);
        s1 += __shfl_xor_sync(0xffffffffu, s1, off);
        s2 += __shfl_xor_sync(0xffffffffu, s2, off);
        s3 += __shfl_xor_sync(0xffffffffu, s3, off);
    }
    if (lane == 0) {
        s0 += bp2[0]; s1 += bp2[1]; s2 += bp2[2]; s3 += bp2[3];
        float4 o = {s0, s1, s2, s3};
        *(float4*)&g_plog[node * 4] = o;
        unsigned int m = max(max(fenc(s0), fenc(s1)), max(fenc(s2), fenc(s3)));
        atomicMax(&g_gmax, m);
    }
}

__global__ void k_sm1() {
    int idx = blockIdx.x * blockDim.x + threadIdx.x;
    float gm = fdec(g_gmax);
    float ex = 0.f;
    if (idx < Nn * 4) {
        ex = __expf(g_plog[idx] - gm);
        g_plog[idx] = ex;
    }
    #pragma unroll
    for (int off = 16; off; off >>= 1) ex += __shfl_xor_sync(0xffffffffu, ex, off);
    __shared__ float ws[8];
    if ((threadIdx.x & 31) == 0) ws[threadIdx.x >> 5] = ex;
    __syncthreads();
    if (threadIdx.x == 0) {
        float tot = 0.f;
        #pragma unroll
        for (int k = 0; k < 8; k++) tot += ws[k];
        atomicAdd(&g_gsum, tot);
    }
}

__global__ void k_sm2(float* __restrict__ out) {
    int idx = blockIdx.x * blockDim.x + threadIdx.x;
    if (idx < Nn * 4) out[idx] = g_plog[idx] / g_gsum;
}

// ---------------- host ------------------------------------------------------
extern "C" void kernel_launch(void* const* d_in, const int* in_sizes, int n_in,
                              void* d_out, int out_size) {
    const float* x    = (const float*)d_in[0];
    const int*   ei   = (const int*)  d_in[1];
    const float* eat  = (const float*)d_in[2];
    const float* Wl1  = (const float*)d_in[3];
    const float* bl1  = (const float*)d_in[4];
    const float* Wr1  = (const float*)d_in[5];
    const float* br1  = (const float*)d_in[6];
    const float* We1  = (const float*)d_in[7];
    const float* att1 = (const float*)d_in[8];
    const float* bias1= (const float*)d_in[9];
    const float* g1   = (const float*)d_in[10];
    const float* be1  = (const float*)d_in[11];
    const float* Wl2  = (const float*)d_in[12];
    const float* bl2  = (const float*)d_in[13];
    const float* Wr2  = (const float*)d_in[14];
    const float* br2  = (const float*)d_in[15];
    const float* We2  = (const float*)d_in[16];
    const float* att2 = (const float*)d_in[17];
    const float* bias2= (const float*)d_in[18];
    const float* g2   = (const float*)d_in[19];
    const float* be2  = (const float*)d_in[20];
    const float* Wp1  = (const float*)d_in[21];
    const float* bp1  = (const float*)d_in[22];
    const float* Wp2  = (const float*)d_in[23];
    const float* bp2  = (const float*)d_in[24];
    float* out = (float*)d_out;

    void *p_h, *p_h2, *p_xl;
    cudaGetSymbolAddress(&p_h,  g_h);
    cudaGetSymbolAddress(&p_h2, g_h2);
    cudaGetSymbolAddress(&p_xl, g_xl);

    const int MT = (Nn + 63) / 64;   // 157 m-tiles

    k_init<<<(Nn + 255) / 256, 256>>>();
    k_lin1<<<(Nn * HID + 255) / 256, 256>>>(x, Wl1, bl1, Wr1, br1);
    k_deg<<<(Ee + 255) / 256, 256>>>(ei, eat);
    k_scan<<<1, 1024>>>();
    k_scatter<<<(EA + 255) / 256, 256>>>(ei, eat);

    // conv1
    k_conv1<<<(Nn + 3) / 4, 128>>>(We1, att1);
    k_ln_relu<<<(Nn + 7) / 8, 256>>>((const float*)p_h, (float*)p_h, bias1, g1, be1);

    // conv2
    k_gemm2<<<dim3(MT, 4), 256>>>((const float*)p_h, Wl2, bl2, Wr2, br2);
    k_conv2<<<(Nn + 3) / 4, 128>>>(We2, att2);
    k_ln_relu<<<(Nn + 7) / 8, 256>>>((const float*)p_h2, (float*)p_h2, bias2, g2, be2);

    // policy head: p1 = relu(h2 @ Wp1 + bp1) into g_xl, then 128->4 + max
    k_sgemm<1><<<dim3(MT, 1), 256>>>((const float*)p_h2, Wp1, bp1, (float*)p_xl, 128);
    k_pol2<<<(Nn + 7) / 8, 256>>>(Wp2, bp2);

    // global softmax
    k_sm1<<<(Nn * 4 + 255) / 256, 256>>>();
    k_sm2<<<(Nn * 4 + 255) / 256, 256>>>(out);
}

// round 17
// speedup vs baseline: 1.1453x; 1.1453x over previous
#include <cuda_runtime.h>

#define Nn 10000
#define Ee 320000
#define EA (Ee + Nn)
#define HID 256
#define LIN1_T (Nn * HID)

// ---------------- scratch (static device globals; zero-initialized) --------
__device__ __align__(16) float g_xl[Nn * HID];
__device__ __align__(16) float g_xr[Nn * HID];
__device__ __align__(16) float g_h [Nn * HID];
__device__ __align__(16) float g_h2[Nn * HID];
__device__ int          g_cnt[Nn];
__device__ int          g_cur[Nn];
__device__ int          g_rowptr[Nn + 1];
__device__ int          g_csrc[EA];
__device__ float        g_cea[EA];
__device__ float        g_loop[Nn];
__device__ float        g_plog[Nn * 4];
__device__ unsigned int g_gmax;
__device__ float        g_gsum;

// ---------------- helpers ---------------------------------------------------
__device__ __forceinline__ unsigned int fenc(float x) {
    unsigned int u = __float_as_uint(x);
    return (u & 0x80000000u) ? ~u : (u | 0x80000000u);
}
__device__ __forceinline__ float fdec(unsigned int e) {
    return __uint_as_float((e & 0x80000000u) ? (e & 0x7FFFFFFFu) : ~e);
}
__device__ __forceinline__ float lrelu(float x) { return x > 0.f ? x : 0.2f * x; }

__device__ __forceinline__ float logit8(float4 a0, float4 a1, float4 b0, float4 b1,
                                        float ea, float4 w0, float4 w1,
                                        float4 t0, float4 t1) {
    float p;
    p  = lrelu(a0.x + b0.x + ea * w0.x) * t0.x;
    p += lrelu(a0.y + b0.y + ea * w0.y) * t0.y;
    p += lrelu(a0.z + b0.z + ea * w0.z) * t0.z;
    p += lrelu(a0.w + b0.w + ea * w0.w) * t0.w;
    p += lrelu(a1.x + b1.x + ea * w1.x) * t1.x;
    p += lrelu(a1.y + b1.y + ea * w1.y) * t1.y;
    p += lrelu(a1.z + b1.z + ea * w1.z) * t1.z;
    p += lrelu(a1.w + b1.w + ea * w1.w) * t1.w;
    return p;
}

// ---------------- fused conv1 linear + degree count --------------------------
// threads [0, LIN1_T): lin1 (x @ Wl/Wr).  threads [LIN1_T, LIN1_T+Ee): degree.
// Relies on g_cnt/g_loop being zero (initial load state, re-zeroed by k_tail).
__global__ void k_lin1deg(const float* __restrict__ x,
                          const float* __restrict__ Wl, const float* __restrict__ bl,
                          const float* __restrict__ Wr, const float* __restrict__ br,
                          const int* __restrict__ ei, const float* __restrict__ eat) {
    int idx = blockIdx.x * blockDim.x + threadIdx.x;
    if (idx < LIN1_T) {
        int i = idx >> 8, j = idx & 255;
        float x0 = x[i * 4], x1 = x[i * 4 + 1], x2 = x[i * 4 + 2], x3 = x[i * 4 + 3];
        g_xl[idx] = x0 * Wl[j] + x1 * Wl[256 + j] + x2 * Wl[512 + j] + x3 * Wl[768 + j] + bl[j];
        g_xr[idx] = x0 * Wr[j] + x1 * Wr[256 + j] + x2 * Wr[512 + j] + x3 * Wr[768 + j] + br[j];
    } else {
        int e = idx - LIN1_T;
        if (e < Ee) {
            int d = ei[Ee + e];
            atomicAdd(&g_cnt[d], 1);
            atomicAdd(&g_loop[d], eat[e]);
        }
    }
}

// exclusive scan of (cnt[i]+1) -> rowptr; smem-staged coalesced loads.
__global__ void k_scan() {
    __shared__ int stage[10240];
    __shared__ int wsum[32];
    int t = threadIdx.x;
    int lane = t & 31, wid = t >> 5;
    #pragma unroll
    for (int k = 0; k < 10; k++) {
        int idx = k * 1024 + t;
        int v = 0;
        if (idx < Nn) {
            int c = g_cnt[idx];
            v = c + 1;
            g_loop[idx] = __fdividef(g_loop[idx], fmaxf((float)c, 1.0f));
        }
        stage[idx] = v;
    }
    __syncthreads();
    int base = t * 10;
    int local[10];
    int s = 0;
    #pragma unroll
    for (int k = 0; k < 10; k++) {
        local[k] = s;
        s += stage[base + k];
    }
    int inc = s;
    #pragma unroll
    for (int off = 1; off < 32; off <<= 1) {
        int u = __shfl_up_sync(0xffffffffu, inc, off);
        if (lane >= off) inc += u;
    }
    if (lane == 31) wsum[wid] = inc;
    __syncthreads();
    if (wid == 0) {
        int w = wsum[lane];
        #pragma unroll
        for (int off = 1; off < 32; off <<= 1) {
            int u = __shfl_up_sync(0xffffffffu, w, off);
            if (lane >= off) w += u;
        }
        wsum[lane] = w;
    }
    __syncthreads();
    int offset = inc - s + (wid ? wsum[wid - 1] : 0);
    #pragma unroll
    for (int k = 0; k < 10; k++) {
        int idx = base + k;
        if (idx < Nn) g_rowptr[idx] = offset + local[k];
    }
    if (t == 1023) g_rowptr[Nn] = wsum[31];
}

// scatter edges + self-loops in one launch
__global__ void k_scatter(const int* __restrict__ ei, const float* __restrict__ eat) {
    int e = blockIdx.x * blockDim.x + threadIdx.x;
    if (e < Ee) {
        int d = ei[Ee + e];
        int pos = g_rowptr[d] + atomicAdd(&g_cur[d], 1);
        g_csrc[pos] = ei[e];
        g_cea[pos]  = eat[e];
    } else if (e < EA) {
        int i = e - Ee;
        int pos = g_rowptr[i + 1] - 1;
        g_csrc[pos] = i;
        g_cea[pos]  = g_loop[i];
    }
}

// ---------------- fused convs: dual-state online softmax (R9 win, verbatim) --
__global__ __launch_bounds__(128) void k_conv1(const float* __restrict__ We,
                                               const float* __restrict__ att) {
    int node = (blockIdx.x * blockDim.x + threadIdx.x) >> 5;
    if (node >= Nn) return;
    int lane = threadIdx.x & 31;
    int c0 = lane * 8;
    float4 b0 = *(const float4*)&g_xr[node * HID + c0];
    float4 b1 = *(const float4*)&g_xr[node * HID + c0 + 4];
    float4 w0 = *(const float4*)&We[c0];
    float4 w1 = *(const float4*)&We[c0 + 4];
    float4 t0 = *(const float4*)&att[c0];
    float4 t1 = *(const float4*)&att[c0 + 4];
    float mxA = -3.4e38f, denA = 0.f;
    float mxB = -3.4e38f, denB = 0.f;
    float4 aA0 = {0,0,0,0}, aA1 = {0,0,0,0};
    float4 aB0 = {0,0,0,0}, aB1 = {0,0,0,0};
    int j0 = g_rowptr[node], j1 = g_rowptr[node + 1];
    int n = j1 - j0;
    int j = j0;
    for (int it = 0; it < (n >> 1); it++, j += 2) {
        int sA = g_csrc[j], sB = g_csrc[j + 1];
        float eaA = g_cea[j], eaB = g_cea[j + 1];
        float4 fA0 = *(const float4*)&g_xl[sA * HID + c0];
        float4 fA1 = *(const float4*)&g_xl[sA * HID + c0 + 4];
        float4 fB0 = *(const float4*)&g_xl[sB * HID + c0];
        float4 fB1 = *(const float4*)&g_xl[sB * HID + c0 + 4];
        float pA = logit8(fA0, fA1, b0, b1, eaA, w0, w1, t0, t1);
        float pB = logit8(fB0, fB1, b0, b1, eaB, w0, w1, t0, t1);
        pA += __shfl_xor_sync(0xffffffffu, pA, 1);
        pB += __shfl_xor_sync(0xffffffffu, pB, 1);
        pA += __shfl_xor_sync(0xffffffffu, pA, 2);
        pB += __shfl_xor_sync(0xffffffffu, pB, 2);
        pA += __shfl_xor_sync(0xffffffffu, pA, 4);
        pB += __shfl_xor_sync(0xffffffffu, pB, 4);
        float nmA = fmaxf(mxA, pA), nmB = fmaxf(mxB, pB);
        float scA = __expf(mxA - nmA), scB = __expf(mxB - nmB);
        float peA = __expf(pA - nmA), peB = __expf(pB - nmB);
        denA = denA * scA + peA;           denB = denB * scB + peB;
        aA0.x = aA0.x * scA + peA * fA0.x; aB0.x = aB0.x * scB + peB * fB0.x;
        aA0.y = aA0.y * scA + peA * fA0.y; aB0.y = aB0.y * scB + peB * fB0.y;
        aA0.z = aA0.z * scA + peA * fA0.z; aB0.z = aB0.z * scB + peB * fB0.z;
        aA0.w = aA0.w * scA + peA * fA0.w; aB0.w = aB0.w * scB + peB * fB0.w;
        aA1.x = aA1.x * scA + peA * fA1.x; aB1.x = aB1.x * scB + peB * fB1.x;
        aA1.y = aA1.y * scA + peA * fA1.y; aB1.y = aB1.y * scB + peB * fB1.y;
        aA1.z = aA1.z * scA + peA * fA1.z; aB1.z = aB1.z * scB + peB * fB1.z;
        aA1.w = aA1.w * scA + peA * fA1.w; aB1.w = aB1.w * scB + peB * fB1.w;
        mxA = nmA; mxB = nmB;
    }
    if (n & 1) {
        int sA = g_csrc[j];
        float eaA = g_cea[j];
        float4 fA0 = *(const float4*)&g_xl[sA * HID + c0];
        float4 fA1 = *(const float4*)&g_xl[sA * HID + c0 + 4];
        float pA = logit8(fA0, fA1, b0, b1, eaA, w0, w1, t0, t1);
        pA += __shfl_xor_sync(0xffffffffu, pA, 1);
        pA += __shfl_xor_sync(0xffffffffu, pA, 2);
        pA += __shfl_xor_sync(0xffffffffu, pA, 4);
        float nmA = fmaxf(mxA, pA);
        float scA = __expf(mxA - nmA);
        float peA = __expf(pA - nmA);
        denA = denA * scA + peA;
        aA0.x = aA0.x * scA + peA * fA0.x;
        aA0.y = aA0.y * scA + peA * fA0.y;
        aA0.z = aA0.z * scA + peA * fA0.z;
        aA0.w = aA0.w * scA + peA * fA0.w;
        aA1.x = aA1.x * scA + peA * fA1.x;
        aA1.y = aA1.y * scA + peA * fA1.y;
        aA1.z = aA1.z * scA + peA * fA1.z;
        aA1.w = aA1.w * scA + peA * fA1.w;
        mxA = nmA;
    }
    float nm = fmaxf(mxA, mxB);
    float sA = __expf(mxA - nm), sB = __expf(mxB - nm);
    float inv = 1.0f / (denA * sA + denB * sB);
    float4 o0, o1;
    o0.x = (aA0.x * sA + aB0.x * sB) * inv;
    o0.y = (aA0.y * sA + aB0.y * sB) * inv;
    o0.z = (aA0.z * sA + aB0.z * sB) * inv;
    o0.w = (aA0.w * sA + aB0.w * sB) * inv;
    o1.x = (aA1.x * sA + aB1.x * sB) * inv;
    o1.y = (aA1.y * sA + aB1.y * sB) * inv;
    o1.z = (aA1.z * sA + aB1.z * sB) * inv;
    o1.w = (aA1.w * sA + aB1.w * sB) * inv;
    *(float4*)&g_h[node * HID + c0]     = o0;
    *(float4*)&g_h[node * HID + c0 + 4] = o1;
}

__global__ __launch_bounds__(128) void k_conv2(const float* __restrict__ We,
                                               const float* __restrict__ att) {
    int node = (blockIdx.x * blockDim.x + threadIdx.x) >> 5;
    if (node >= Nn) return;
    int lane = threadIdx.x & 31;
    int c0 = lane * 8;
    float4 b0 = *(const float4*)&g_xr[node * HID + c0];
    float4 b1 = *(const float4*)&g_xr[node * HID + c0 + 4];
    float4 w0 = *(const float4*)&We[c0];
    float4 w1 = *(const float4*)&We[c0 + 4];
    float4 t0 = *(const float4*)&att[c0];
    float4 t1 = *(const float4*)&att[c0 + 4];
    float mxA = -3.4e38f, denA = 0.f;
    float mxB = -3.4e38f, denB = 0.f;
    float4 aA0 = {0,0,0,0}, aA1 = {0,0,0,0};
    float4 aB0 = {0,0,0,0}, aB1 = {0,0,0,0};
    int j0 = g_rowptr[node], j1 = g_rowptr[node + 1];
    int n = j1 - j0;
    int j = j0;
    for (int it = 0; it < (n >> 1); it++, j += 2) {
        int sA = g_csrc[j], sB = g_csrc[j + 1];
        float eaA = g_cea[j], eaB = g_cea[j + 1];
        float4 fA0 = *(const float4*)&g_xl[sA * HID + c0];
        float4 fA1 = *(const float4*)&g_xl[sA * HID + c0 + 4];
        float4 fB0 = *(const float4*)&g_xl[sB * HID + c0];
        float4 fB1 = *(const float4*)&g_xl[sB * HID + c0 + 4];
        float pA = logit8(fA0, fA1, b0, b1, eaA, w0, w1, t0, t1);
        float pB = logit8(fB0, fB1, b0, b1, eaB, w0, w1, t0, t1);
        #pragma unroll
        for (int off = 16; off; off >>= 1) {
            pA += __shfl_xor_sync(0xffffffffu, pA, off);
            pB += __shfl_xor_sync(0xffffffffu, pB, off);
        }
        float nmA = fmaxf(mxA, pA), nmB = fmaxf(mxB, pB);
        float scA = __expf(mxA - nmA), scB = __expf(mxB - nmB);
        float peA = __expf(pA - nmA), peB = __expf(pB - nmB);
        denA = denA * scA + peA;           denB = denB * scB + peB;
        aA0.x = aA0.x * scA + peA * fA0.x; aB0.x = aB0.x * scB + peB * fB0.x;
        aA0.y = aA0.y * scA + peA * fA0.y; aB0.y = aB0.y * scB + peB * fB0.y;
        aA0.z = aA0.z * scA + peA * fA0.z; aB0.z = aB0.z * scB + peB * fB0.z;
        aA0.w = aA0.w * scA + peA * fA0.w; aB0.w = aB0.w * scB + peB * fB0.w;
        aA1.x = aA1.x * scA + peA * fA1.x; aB1.x = aB1.x * scB + peB * fB1.x;
        aA1.y = aA1.y * scA + peA * fA1.y; aB1.y = aB1.y * scB + peB * fB1.y;
        aA1.z = aA1.z * scA + peA * fA1.z; aB1.z = aB1.z * scB + peB * fB1.z;
        aA1.w = aA1.w * scA + peA * fA1.w; aB1.w = aB1.w * scB + peB * fB1.w;
        mxA = nmA; mxB = nmB;
    }
    if (n & 1) {
        int sA = g_csrc[j];
        float eaA = g_cea[j];
        float4 fA0 = *(const float4*)&g_xl[sA * HID + c0];
        float4 fA1 = *(const float4*)&g_xl[sA * HID + c0 + 4];
        float pA = logit8(fA0, fA1, b0, b1, eaA, w0, w1, t0, t1);
        #pragma unroll
        for (int off = 16; off; off >>= 1) pA += __shfl_xor_sync(0xffffffffu, pA, off);
        float nmA = fmaxf(mxA, pA);
        float scA = __expf(mxA - nmA);
        float peA = __expf(pA - nmA);
        denA = denA * scA + peA;
        aA0.x = aA0.x * scA + peA * fA0.x;
        aA0.y = aA0.y * scA + peA * fA0.y;
        aA0.z = aA0.z * scA + peA * fA0.z;
        aA0.w = aA0.w * scA + peA * fA0.w;
        aA1.x = aA1.x * scA + peA * fA1.x;
        aA1.y = aA1.y * scA + peA * fA1.y;
        aA1.z = aA1.z * scA + peA * fA1.z;
        aA1.w = aA1.w * scA + peA * fA1.w;
        mxA = nmA;
    }
    float nm = fmaxf(mxA, mxB);
    float sA = __expf(mxA - nm), sB = __expf(mxB - nm);
    float inv = 1.0f / (denA * sA + denB * sB);
    float4 o0, o1;
    o0.x = (aA0.x * sA + aB0.x * sB) * inv;
    o0.y = (aA0.y * sA + aB0.y * sB) * inv;
    o0.z = (aA0.z * sA + aB0.z * sB) * inv;
    o0.w = (aA0.w * sA + aB0.w * sB) * inv;
    o1.x = (aA1.x * sA + aB1.x * sB) * inv;
    o1.y = (aA1.y * sA + aB1.y * sB) * inv;
    o1.z = (aA1.z * sA + aB1.z * sB) * inv;
    o1.w = (aA1.w * sA + aB1.w * sB) * inv;
    *(float4*)&g_h2[node * HID + c0]     = o0;
    *(float4*)&g_h2[node * HID + c0 + 4] = o1;
}

// layernorm(in + bias) * g + b, then relu.  One warp per node.
__global__ void k_ln_relu(const float* __restrict__ inp, float* __restrict__ outp,
                          const float* __restrict__ bias, const float* __restrict__ gam,
                          const float* __restrict__ bet) {
    int w = (blockIdx.x * blockDim.x + threadIdx.x) >> 5;
    if (w >= Nn) return;
    int lane = threadIdx.x & 31, c0 = lane * 8;
    float v[8];
    float4 p0 = *(const float4*)&inp[w * HID + c0];
    float4 p1 = *(const float4*)&inp[w * HID + c0 + 4];
    float4 q0 = *(const float4*)&bias[c0];
    float4 q1 = *(const float4*)&bias[c0 + 4];
    v[0] = p0.x + q0.x; v[1] = p0.y + q0.y; v[2] = p0.z + q0.z; v[3] = p0.w + q0.w;
    v[4] = p1.x + q1.x; v[5] = p1.y + q1.y; v[6] = p1.z + q1.z; v[7] = p1.w + q1.w;
    float s = 0.f;
    #pragma unroll
    for (int k = 0; k < 8; k++) s += v[k];
    #pragma unroll
    for (int off = 16; off; off >>= 1) s += __shfl_xor_sync(0xffffffffu, s, off);
    float mu = s * (1.0f / HID);
    float q = 0.f;
    #pragma unroll
    for (int k = 0; k < 8; k++) { float t = v[k] - mu; q += t * t; }
    #pragma unroll
    for (int off = 16; off; off >>= 1) q += __shfl_xor_sync(0xffffffffu, q, off);
    float r = rsqrtf(q * (1.0f / HID) + 1e-5f);
    float4 go0 = *(const float4*)&gam[c0];
    float4 go1 = *(const float4*)&gam[c0 + 4];
    float4 bo0 = *(const float4*)&bet[c0];
    float4 bo1 = *(const float4*)&bet[c0 + 4];
    float4 o0, o1;
    o0.x = fmaxf((v[0] - mu) * r * go0.x + bo0.x, 0.f);
    o0.y = fmaxf((v[1] - mu) * r * go0.y + bo0.y, 0.f);
    o0.z = fmaxf((v[2] - mu) * r * go0.z + bo0.z, 0.f);
    o0.w = fmaxf((v[3] - mu) * r * go0.w + bo0.w, 0.f);
    o1.x = fmaxf((v[4] - mu) * r * go1.x + bo1.x, 0.f);
    o1.y = fmaxf((v[5] - mu) * r * go1.y + bo1.y, 0.f);
    o1.z = fmaxf((v[6] - mu) * r * go1.z + bo1.z, 0.f);
    o1.w = fmaxf((v[7] - mu) * r * go1.w + bo1.w, 0.f);
    *(float4*)&outp[w * HID + c0]     = o0;
    *(float4*)&outp[w * HID + c0 + 4] = o1;
}

// conv2 linears: g_h [N,256] @ W [256,256] + b -> g_xl (y=0) / g_xr (y=1)
// (R9 version — measured fastest so far)
__global__ void k_gemm(const float* __restrict__ Hin,
                       const float* __restrict__ W0, const float* __restrict__ b0,
                       const float* __restrict__ W1, const float* __restrict__ b1) {
    __shared__ float sh[32][HID];
    const float* W  = blockIdx.y ? W1 : W0;
    const float* bb = blockIdx.y ? b1 : b0;
    float* O        = blockIdx.y ? g_xr : g_xl;
    int i0 = blockIdx.x * 32;
    int t = threadIdx.x;
    for (int idx = t; idx < 32 * HID; idx += 256) {
        int r = idx >> 8, c = idx & 255;
        sh[r][c] = (i0 + r < Nn) ? Hin[(i0 + r) * HID + c] : 0.f;
    }
    __syncthreads();
    float acc[32];
    #pragma unroll
    for (int i = 0; i < 32; i++) acc[i] = 0.f;
    for (int k = 0; k < HID; k += 4) {
        float w0 = W[k * HID + t];
        float w1 = W[(k + 1) * HID + t];
        float w2 = W[(k + 2) * HID + t];
        float w3 = W[(k + 3) * HID + t];
        #pragma unroll
        for (int i = 0; i < 32; i++) {
            float4 hv = *(const float4*)&sh[i][k];
            acc[i] += hv.x * w0 + hv.y * w1 + hv.z * w2 + hv.w * w3;
        }
    }
    float bj = bb[t];
    #pragma unroll
    for (int i = 0; i < 32; i++)
        if (i0 + i < Nn) O[(i0 + i) * HID + t] = acc[i] + bj;
}

// policy head: relu(h2 @ Wp1 + bp1) @ Wp2 + bp2 -> g_plog, plus global max
__global__ void k_policy(const float* __restrict__ Wp1, const float* __restrict__ bp1,
                         const float* __restrict__ Wp2, const float* __restrict__ bp2) {
    __shared__ float sh[32][HID];
    int i0 = blockIdx.x * 32;
    int t = threadIdx.x;                   // 128 threads
    for (int idx = t; idx < 32 * HID; idx += 128) {
        int r = idx >> 8, c = idx & 255;
        sh[r][c] = (i0 + r < Nn) ? g_h2[(i0 + r) * HID + c] : 0.f;
    }
    __syncthreads();
    float acc[32];
    #pragma unroll
    for (int i = 0; i < 32; i++) acc[i] = 0.f;
    for (int k = 0; k < HID; k += 4) {
        float w0 = Wp1[k * 128 + t];
        float w1 = Wp1[(k + 1) * 128 + t];
        float w2 = Wp1[(k + 2) * 128 + t];
        float w3 = Wp1[(k + 3) * 128 + t];
        #pragma unroll
        for (int i = 0; i < 32; i++) {
            float4 hv = *(const float4*)&sh[i][k];
            acc[i] += hv.x * w0 + hv.y * w1 + hv.z * w2 + hv.w * w3;
        }
    }
    float b = bp1[t];
    __syncthreads();
    float* p1 = &sh[0][0];
    #pragma unroll
    for (int i = 0; i < 32; i++) p1[i * 129 + t] = fmaxf(acc[i] + b, 0.f);
    __syncthreads();
    int node = t >> 2, c = t & 3;
    float s = bp2[c];
    for (int j = 0; j < 128; j++) s += p1[node * 129 + j] * Wp2[j * 4 + c];
    bool valid = (i0 + node) < Nn;
    if (valid) g_plog[(i0 + node) * 4 + c] = s;
    unsigned int m = valid ? fenc(s) : 0u;
    #pragma unroll
    for (int off = 16; off; off >>= 1) m = max(m, __shfl_xor_sync(0xffffffffu, m, off));
    if ((t & 31) == 0) atomicMax(&g_gmax, m);
}

__global__ void k_sm1() {
    int idx = blockIdx.x * blockDim.x + threadIdx.x;
    float gm = fdec(g_gmax);
    float ex = 0.f;
    if (idx < Nn * 4) {
        ex = __expf(g_plog[idx] - gm);
        g_plog[idx] = ex;
    }
    #pragma unroll
    for (int off = 16; off; off >>= 1) ex += __shfl_xor_sync(0xffffffffu, ex, off);
    __shared__ float ws[8];
    if ((threadIdx.x & 31) == 0) ws[threadIdx.x >> 5] = ex;
    __syncthreads();
    if (threadIdx.x == 0) {
        float tot = 0.f;
        #pragma unroll
        for (int k = 0; k < 8; k++) tot += ws[k];
        atomicAdd(&g_gsum, tot);
    }
}

__global__ void k_sm2(float* __restrict__ out) {
    int idx = blockIdx.x * blockDim.x + threadIdx.x;
    if (idx < Nn * 4) out[idx] = g_plog[idx] / g_gsum;
}

// tail: re-zero scratch for the next graph replay (globals start zeroed at load)
__global__ void k_tail() {
    int i = blockIdx.x * blockDim.x + threadIdx.x;
    if (i < Nn) { g_cnt[i] = 0; g_cur[i] = 0; g_loop[i] = 0.f; }
    if (i == 0) { g_gmax = 0u; g_gsum = 0.f; }
}

// ---------------- host ------------------------------------------------------
extern "C" void kernel_launch(void* const* d_in, const int* in_sizes, int n_in,
                              void* d_out, int out_size) {
    const float* x    = (const float*)d_in[0];
    const int*   ei   = (const int*)  d_in[1];
    const float* eat  = (const float*)d_in[2];
    const float* Wl1  = (const float*)d_in[3];
    const float* bl1  = (const float*)d_in[4];
    const float* Wr1  = (const float*)d_in[5];
    const float* br1  = (const float*)d_in[6];
    const float* We1  = (const float*)d_in[7];
    const float* att1 = (const float*)d_in[8];
    const float* bias1= (const float*)d_in[9];
    const float* g1   = (const float*)d_in[10];
    const float* be1  = (const float*)d_in[11];
    const float* Wl2  = (const float*)d_in[12];
    const float* bl2  = (const float*)d_in[13];
    const float* Wr2  = (const float*)d_in[14];
    const float* br2  = (const float*)d_in[15];
    const float* We2  = (const float*)d_in[16];
    const float* att2 = (const float*)d_in[17];
    const float* bias2= (const float*)d_in[18];
    const float* g2   = (const float*)d_in[19];
    const float* be2  = (const float*)d_in[20];
    const float* Wp1  = (const float*)d_in[21];
    const float* bp1  = (const float*)d_in[22];
    const float* Wp2  = (const float*)d_in[23];
    const float* bp2  = (const float*)d_in[24];
    float* out = (float*)d_out;

    void *p_h, *p_h2;
    cudaGetSymbolAddress(&p_h,  g_h);
    cudaGetSymbolAddress(&p_h2, g_h2);

    // 1: fused lin1 + degree   2: scan   3: scatter   4: conv1 (ncu target)
    k_lin1deg<<<(LIN1_T + Ee + 255) / 256, 256>>>(x, Wl1, bl1, Wr1, br1, ei, eat);
    k_scan<<<1, 1024>>>();
    k_scatter<<<(EA + 255) / 256, 256>>>(ei, eat);
    k_conv1<<<(Nn + 3) / 4, 128>>>(We1, att1);

    k_ln_relu<<<(Nn + 7) / 8, 256>>>((const float*)p_h, (float*)p_h, bias1, g1, be1);

    // conv2
    k_gemm<<<dim3((Nn + 31) / 32, 2), 256>>>((const float*)p_h, Wl2, bl2, Wr2, br2);
    k_conv2<<<(Nn + 3) / 4, 128>>>(We2, att2);
    k_ln_relu<<<(Nn + 7) / 8, 256>>>((const float*)p_h2, (float*)p_h2, bias2, g2, be2);

    // policy head + global softmax
    k_policy<<<(Nn + 31) / 32, 128>>>(Wp1, bp1, Wp2, bp2);
    k_sm1<<<(Nn * 4 + 255) / 256, 256>>>();
    k_sm2<<<(Nn * 4 + 255) / 256, 256>>>(out);

    // re-zero scratch for next replay
    k_tail<<<(Nn + 255) / 256, 256>>>();
}